// round 1
// baseline (speedup 1.0000x reference)
#include <cuda_runtime.h>

// ---------------------------------------------------------------------------
// QConv2d: new_rho[b] = U2 @ rho[b] @ U2^T,  U2[g*64+v, f*64+w] = uc[g,f+2]*W[v,w]
// W = kron(ux, uy) (64x64).  Factored:
//   A: M1[f]      = W @ rho[f-block]            (2 x [64x64]@[64x128])
//   B: M2[f,f']   = M1[f][:, f'-block] @ W^T    (4 x 64^3)
//   C: out[g*64+v, g'*64+v'] = sum_{f,f'} uc2[g,f] uc2[g',f'] M2[f,f'][v,v']
// ---------------------------------------------------------------------------

// smem layout in floats:
//  [0      .. 16383]  rho (stage A input); aliased by M2 [ff'][v][v'] in stage B
//  [16384 .. 20479]  W  [v][w]
//  [20480 .. 24575]  Wt [w][v]
//  [24576 .. 40959]  M1t [f][c][v]   (c = f'*64 + w', 2*128*64)
#define SM_RHO 0
#define SM_W   16384
#define SM_WT  20480
#define SM_M1  24576
#define SMEM_BYTES (40960 * 4)

__global__ void __launch_bounds__(256, 1)
qconv_kernel(const float* __restrict__ rho,
             const float* __restrict__ ux,
             const float* __restrict__ uy,
             const float* __restrict__ uc,
             float* __restrict__ out)
{
    extern __shared__ float s[];
    const int b   = blockIdx.x;
    const int tid = threadIdx.x;

    // ---- load rho[b] (16384 floats) into smem, vectorized ----
    {
        const float4* src = (const float4*)(rho + (size_t)b * 16384);
        float4* dst = (float4*)(s + SM_RHO);
        #pragma unroll
        for (int i = 0; i < 16; ++i)
            dst[tid + i * 256] = src[tid + i * 256];
    }

    // ---- compute W = kron(ux, uy) and its transpose ----
    #pragma unroll
    for (int e = 0; e < 16; ++e) {
        int id = tid + e * 256;           // 0..4095
        int v = id >> 6, w = id & 63;
        float val = ux[(v >> 3) * 8 + (w >> 3)] * uy[(v & 7) * 8 + (w & 7)];
        s[SM_W  + v * 64 + w] = val;
        s[SM_WT + w * 64 + v] = val;
    }
    __syncthreads();

    // ---- Stage A: M1t[f][c][v] = sum_w W[v][w] * rho[f*64+w][c] ----
    {
        const int f  = tid >> 7;                  // 0..1
        const int v0 = ((tid >> 4) & 7) * 8;      // row tile
        const int c0 = (tid & 15) * 8;            // col tile (c = f'*64+w')
        float acc[8][8];
        #pragma unroll
        for (int i = 0; i < 8; ++i)
            #pragma unroll
            for (int j = 0; j < 8; ++j) acc[i][j] = 0.f;

        const float* Wt = s + SM_WT;
        const float* R  = s + SM_RHO + f * (64 * 128);
        #pragma unroll 4
        for (int k = 0; k < 64; ++k) {
            float4 a0 = *(const float4*)(Wt + k * 64 + v0);
            float4 a1 = *(const float4*)(Wt + k * 64 + v0 + 4);
            float4 q0 = *(const float4*)(R  + k * 128 + c0);
            float4 q1 = *(const float4*)(R  + k * 128 + c0 + 4);
            float av[8] = {a0.x, a0.y, a0.z, a0.w, a1.x, a1.y, a1.z, a1.w};
            float bv[8] = {q0.x, q0.y, q0.z, q0.w, q1.x, q1.y, q1.z, q1.w};
            #pragma unroll
            for (int i = 0; i < 8; ++i)
                #pragma unroll
                for (int j = 0; j < 8; ++j)
                    acc[i][j] = fmaf(av[i], bv[j], acc[i][j]);
        }
        // store transposed: M1t[f][c0+j][v0 + i]  -> float4 contiguous in v
        float* M1 = s + SM_M1 + f * (128 * 64);
        #pragma unroll
        for (int j = 0; j < 8; ++j) {
            float4 t0 = make_float4(acc[0][j], acc[1][j], acc[2][j], acc[3][j]);
            float4 t1 = make_float4(acc[4][j], acc[5][j], acc[6][j], acc[7][j]);
            *(float4*)(M1 + (c0 + j) * 64 + v0)     = t0;
            *(float4*)(M1 + (c0 + j) * 64 + v0 + 4) = t1;
        }
    }
    __syncthreads();   // M1 complete; rho no longer needed -> M2 may alias it

    // ---- Stage B: M2[ff'][v][v'] = sum_k M1t[f][f'*64+k][v] * Wt[k][v'] ----
    {
        const int ffp = tid >> 6;                 // f*2 + f'
        const int f   = ffp >> 1;
        const int fp  = ffp & 1;
        const int v0  = ((tid >> 3) & 7) * 8;
        const int vp0 = (tid & 7) * 8;
        float acc[8][8];
        #pragma unroll
        for (int i = 0; i < 8; ++i)
            #pragma unroll
            for (int j = 0; j < 8; ++j) acc[i][j] = 0.f;

        const float* M1 = s + SM_M1 + f * 8192 + fp * 4096;   // + k*64 + v
        const float* Wt = s + SM_WT;
        #pragma unroll 4
        for (int k = 0; k < 64; ++k) {
            float4 a0 = *(const float4*)(M1 + k * 64 + v0);
            float4 a1 = *(const float4*)(M1 + k * 64 + v0 + 4);
            float4 q0 = *(const float4*)(Wt + k * 64 + vp0);
            float4 q1 = *(const float4*)(Wt + k * 64 + vp0 + 4);
            float av[8] = {a0.x, a0.y, a0.z, a0.w, a1.x, a1.y, a1.z, a1.w};
            float bv[8] = {q0.x, q0.y, q0.z, q0.w, q1.x, q1.y, q1.z, q1.w};
            #pragma unroll
            for (int i = 0; i < 8; ++i)
                #pragma unroll
                for (int j = 0; j < 8; ++j)
                    acc[i][j] = fmaf(av[i], bv[j], acc[i][j]);
        }
        float* M2 = s + SM_RHO + ffp * 4096;      // [v][v'] 64x64
        #pragma unroll
        for (int i = 0; i < 8; ++i) {
            *(float4*)(M2 + (v0 + i) * 64 + vp0)     =
                make_float4(acc[i][0], acc[i][1], acc[i][2], acc[i][3]);
            *(float4*)(M2 + (v0 + i) * 64 + vp0 + 4) =
                make_float4(acc[i][4], acc[i][5], acc[i][6], acc[i][7]);
        }
    }
    __syncthreads();

    // ---- Stage C: channel mix + coalesced store ----
    {
        float cA[4], cB[4];                        // uc2[g][0], uc2[g][1]
        #pragma unroll
        for (int g = 0; g < 4; ++g) {
            cA[g] = uc[g * 4 + 2];
            cB[g] = uc[g * 4 + 3];
        }
        const int wid  = tid >> 5;
        const int lane = tid & 31;
        const float* M2 = s + SM_RHO;
        float* outb = out + (size_t)b * 65536;

        #pragma unroll 1
        for (int r = 0; r < 32; ++r) {
            const int p = wid * 32 + r;            // output row 0..255
            const int g = p >> 6;
            const int v = p & 63;
            const float g0 = cA[g], g1 = cB[g];
            #pragma unroll
            for (int it = 0; it < 2; ++it) {
                const int gp  = (it << 1) | (lane >> 4);   // g' 0..3
                const int vp0 = (lane & 15) * 4;
                const int off = v * 64 + vp0;
                float4 m00 = *(const float4*)(M2 + 0 * 4096 + off); // f=0,f'=0
                float4 m01 = *(const float4*)(M2 + 1 * 4096 + off); // f=0,f'=1
                float4 m10 = *(const float4*)(M2 + 2 * 4096 + off); // f=1,f'=0
                float4 m11 = *(const float4*)(M2 + 3 * 4096 + off); // f=1,f'=1
                float4 t0, t1, o;
                t0.x = fmaf(g1, m10.x, g0 * m00.x);
                t0.y = fmaf(g1, m10.y, g0 * m00.y);
                t0.z = fmaf(g1, m10.z, g0 * m00.z);
                t0.w = fmaf(g1, m10.w, g0 * m00.w);
                t1.x = fmaf(g1, m11.x, g0 * m01.x);
                t1.y = fmaf(g1, m11.y, g0 * m01.y);
                t1.z = fmaf(g1, m11.z, g0 * m01.z);
                t1.w = fmaf(g1, m11.w, g0 * m01.w);
                const float p0 = cA[gp], p1 = cB[gp];
                o.x = fmaf(p1, t1.x, p0 * t0.x);
                o.y = fmaf(p1, t1.y, p0 * t0.y);
                o.z = fmaf(p1, t1.z, p0 * t0.z);
                o.w = fmaf(p1, t1.w, p0 * t0.w);
                // s = it*128 + lane*4  -> warp writes 512B contiguous
                *(float4*)(outb + p * 256 + gp * 64 + vp0) = o;
            }
        }
    }
}

extern "C" void kernel_launch(void* const* d_in, const int* in_sizes, int n_in,
                              void* d_out, int out_size) {
    const float* rho = (const float*)d_in[0];
    const float* ux  = (const float*)d_in[1];
    const float* uy  = (const float*)d_in[2];
    const float* uc  = (const float*)d_in[3];
    float* out = (float*)d_out;

    const int B = in_sizes[0] >> 14;   // elements / (128*128)

    cudaFuncSetAttribute(qconv_kernel,
                         cudaFuncAttributeMaxDynamicSharedMemorySize, SMEM_BYTES);
    qconv_kernel<<<B, 256, SMEM_BYTES>>>(rho, ux, uy, uc, out);
}

// round 4
// speedup vs baseline: 2.2486x; 2.2486x over previous
#include <cuda_runtime.h>

// ---------------------------------------------------------------------------
// QConv2d: out = (uc2 (x) ux (x) uy) . rho . (uc2 (x) ux (x) uy)^T
//   uc2[g,f] = uc[g, f+2]  (channel-insertion reduces to using cols 2,3 of uc)
// Strategy: four in-place 8x8 transform passes on a padded 128x136 smem tile
//   P1: right uy  (contiguous j' in columns)
//   P2: left  uy  (j in rows, stride P)
//   P3: right ux  (i' in columns, stride 8)
//   P4: left  ux  (i in rows, stride 8P)
// then fused uc2 . M . uc2^T epilogue streamed to gmem.
// Row pad P=136 floats (136 mod 32 == 8) makes all strided lane patterns
// hit 32 distinct banks.
// ---------------------------------------------------------------------------

#define PSTR 136
#define SM_UY 17408
#define SM_UX 17472
#define SM_UC 17536
#define SMEM_BYTES (17544 * 4)   // 70176 B -> 2 CTAs/SM

__global__ void __launch_bounds__(256, 2)
qconv_kernel(const float* __restrict__ rho,
             const float* __restrict__ ux,
             const float* __restrict__ uy,
             const float* __restrict__ uc,
             float* __restrict__ out)
{
    extern __shared__ float s[];
    float* buf = s;
    const int b = blockIdx.x;
    const int t = threadIdx.x;

    // weights into smem; uc2[g][f] = uc[g*4 + 2 + f] stored at SM_UC + g*2+f
    if (t < 64) { s[SM_UY + t] = uy[t]; s[SM_UX + t] = ux[t]; }
    else if (t < 72) { int q = t - 64; s[SM_UC + q] = uc[(q >> 1) * 4 + 2 + (q & 1)]; }

    // load rho[b] into padded buffer
    {
        const float4* src = (const float4*)(rho + (size_t)b * 16384);
        #pragma unroll
        for (int i = 0; i < 16; ++i) {
            int q = t + i * 256;          // float4 index 0..4095
            int r = q >> 5, c4 = q & 31;
            ((float4*)buf)[r * 34 + c4] = src[q];
        }
    }
    __syncthreads();

    // ======================= uy passes (right then left) ====================
    {
        float m[64];
        #pragma unroll
        for (int i = 0; i < 16; ++i)
            ((float4*)m)[i] = ((const float4*)(s + SM_UY))[i];

        // ---- P1: right uy. group (r, f', i'): 8 contiguous floats ----
        #pragma unroll
        for (int it = 0; it < 8; ++it) {
            int idx = t + it * 256;              // 0..2047
            int r = idx >> 4, sub = idx & 15;    // sub = f'*8 + i'
            float* g = buf + r * PSTR + sub * 8;
            float in[8], o[8];
            *(float4*)(in)     = *(const float4*)(g);
            *(float4*)(in + 4) = *(const float4*)(g + 4);
            #pragma unroll
            for (int a = 0; a < 8; ++a) {
                float acc = m[a * 8] * in[0];
                #pragma unroll
                for (int n = 1; n < 8; ++n) acc = fmaf(m[a * 8 + n], in[n], acc);
                o[a] = acc;
            }
            *(float4*)(g)     = *(float4*)(o);
            *(float4*)(g + 4) = *(float4*)(o + 4);
        }
        __syncthreads();

        // ---- P2: left uy. group (f, i, c): elements stride PSTR (along j) ----
        #pragma unroll
        for (int it = 0; it < 8; ++it) {
            int idx = t + it * 256;
            int f = idx >> 10, i8 = (idx >> 7) & 7, c = idx & 127;
            float* g = buf + (f * 64 + i8 * 8) * PSTR + c;
            float in[8], o[8];
            #pragma unroll
            for (int n = 0; n < 8; ++n) in[n] = g[n * PSTR];
            #pragma unroll
            for (int a = 0; a < 8; ++a) {
                float acc = m[a * 8] * in[0];
                #pragma unroll
                for (int n = 1; n < 8; ++n) acc = fmaf(m[a * 8 + n], in[n], acc);
                o[a] = acc;
            }
            #pragma unroll
            for (int a = 0; a < 8; ++a) g[a * PSTR] = o[a];
        }
        __syncthreads();
    }

    // ======================= ux passes (right then left) ====================
    {
        float m[64];
        #pragma unroll
        for (int i = 0; i < 16; ++i)
            ((float4*)m)[i] = ((const float4*)(s + SM_UX))[i];

        // ---- P3: right ux. group (f', r, j'): elements stride 8 (along i') ----
        #pragma unroll
        for (int it = 0; it < 8; ++it) {
            int idx = t + it * 256;
            int fp = idx >> 10, rem = idx & 1023;
            int r = rem >> 3, j = rem & 7;       // lane = (r&3)*8 | j -> 32 banks
            float* g = buf + r * PSTR + fp * 64 + j;
            float in[8], o[8];
            #pragma unroll
            for (int n = 0; n < 8; ++n) in[n] = g[n * 8];
            #pragma unroll
            for (int a = 0; a < 8; ++a) {
                float acc = m[a * 8] * in[0];
                #pragma unroll
                for (int n = 1; n < 8; ++n) acc = fmaf(m[a * 8 + n], in[n], acc);
                o[a] = acc;
            }
            #pragma unroll
            for (int a = 0; a < 8; ++a) g[a * 8] = o[a];
        }
        __syncthreads();

        // ---- P4: left ux. group (f, j, c): elements stride 8*PSTR (along i) ----
        #pragma unroll
        for (int it = 0; it < 8; ++it) {
            int idx = t + it * 256;
            int f = idx >> 10, j = (idx >> 7) & 7, c = idx & 127;
            float* g = buf + (f * 64 + j) * PSTR + c;
            float in[8], o[8];
            #pragma unroll
            for (int n = 0; n < 8; ++n) in[n] = g[n * 8 * PSTR];
            #pragma unroll
            for (int a = 0; a < 8; ++a) {
                float acc = m[a * 8] * in[0];
                #pragma unroll
                for (int n = 1; n < 8; ++n) acc = fmaf(m[a * 8 + n], in[n], acc);
                o[a] = acc;
            }
            #pragma unroll
            for (int a = 0; a < 8; ++a) g[a * 8 * PSTR] = o[a];
        }
        __syncthreads();
    }

    // ========== epilogue: out[gv, g'v'] = sum_{f,f'} c[g,f] c[g',f'] M[fv, f'v'] ==
    {
        const int wid = t >> 5, lane = t & 31;
        const int vp0 = (lane & 15) * 4;
        float* outb = out + (size_t)b * 65536;
        float cg0[4], cg1[4];
        #pragma unroll
        for (int g = 0; g < 4; ++g) {
            cg0[g] = s[SM_UC + g * 2];
            cg1[g] = s[SM_UC + g * 2 + 1];
        }

        #pragma unroll 1
        for (int rr = 0; rr < 32; ++rr) {
            const int p = wid * 32 + rr;       // output row 0..255
            const int g = p >> 6, v = p & 63;
            const float a0 = cg0[g], a1 = cg1[g];
            const float* row0 = buf + v * PSTR;          // f = 0
            const float* row1 = buf + (64 + v) * PSTR;   // f = 1
            float4 m00 = *(const float4*)(row0 + vp0);        // f'=0
            float4 m01 = *(const float4*)(row0 + 64 + vp0);   // f'=1
            float4 m10 = *(const float4*)(row1 + vp0);
            float4 m11 = *(const float4*)(row1 + 64 + vp0);
            float4 t0, t1;
            t0.x = fmaf(a1, m10.x, a0 * m00.x);
            t0.y = fmaf(a1, m10.y, a0 * m00.y);
            t0.z = fmaf(a1, m10.z, a0 * m00.z);
            t0.w = fmaf(a1, m10.w, a0 * m00.w);
            t1.x = fmaf(a1, m11.x, a0 * m01.x);
            t1.y = fmaf(a1, m11.y, a0 * m01.y);
            t1.z = fmaf(a1, m11.z, a0 * m01.z);
            t1.w = fmaf(a1, m11.w, a0 * m01.w);
            #pragma unroll
            for (int it = 0; it < 2; ++it) {
                const int gp = (it << 1) | (lane >> 4);
                const float p0 = cg0[gp], p1 = cg1[gp];
                float4 o;
                o.x = fmaf(p1, t1.x, p0 * t0.x);
                o.y = fmaf(p1, t1.y, p0 * t0.y);
                o.z = fmaf(p1, t1.z, p0 * t0.z);
                o.w = fmaf(p1, t1.w, p0 * t0.w);
                *(float4*)(outb + p * 256 + gp * 64 + vp0) = o;
            }
        }
    }
}

extern "C" void kernel_launch(void* const* d_in, const int* in_sizes, int n_in,
                              void* d_out, int out_size) {
    const float* rho = (const float*)d_in[0];
    const float* ux  = (const float*)d_in[1];
    const float* uy  = (const float*)d_in[2];
    const float* uc  = (const float*)d_in[3];
    float* out = (float*)d_out;

    const int B = in_sizes[0] >> 14;   // elements / (128*128)

    cudaFuncSetAttribute(qconv_kernel,
                         cudaFuncAttributeMaxDynamicSharedMemorySize, SMEM_BYTES);
    qconv_kernel<<<B, 256, SMEM_BYTES>>>(rho, ux, uy, uc, out);
}

// round 5
// speedup vs baseline: 2.2517x; 1.0014x over previous
#include <cuda_runtime.h>

// ---------------------------------------------------------------------------
// QConv2d: out = (uc2 (x) ux (x) uy) . rho . (uc2 (x) ux (x) uy)^T
//   uc2[g,f] = uc[g, f+2]
// Four 8x8 transform passes on a padded 128x136 smem tile, using packed
// f32x2 FMA (2 MACs/instr). P1 is fused with the gmem load.
//   P1': gmem -> right uy (contiguous j') -> smem
//   P2 : left  uy  (stride PSTR)
//   P3 : right ux  (stride 8)
//   P4 : left  ux  (stride 8*PSTR)
// then fused uc2 . M . uc2^T epilogue streamed to gmem.
// ---------------------------------------------------------------------------

#define PSTR 136
#define SM_UY 17408
#define SM_UX 17472
#define SM_UC 17536
#define SMEM_BYTES (17544 * 4)   // 70176 B -> 2 CTAs/SM

typedef unsigned long long u64t;

__device__ __forceinline__ u64t pk2(float lo, float hi) {
    u64t r; asm("mov.b64 %0, {%1,%2};" : "=l"(r) : "f"(lo), "f"(hi)); return r;
}
__device__ __forceinline__ u64t fma2(u64t a, u64t b, u64t c) {
    u64t d; asm("fma.rn.f32x2 %0, %1, %2, %3;" : "=l"(d) : "l"(a), "l"(b), "l"(c));
    return d;
}
__device__ __forceinline__ void upk2(u64t v, float& lo, float& hi) {
    asm("mov.b64 {%0,%1}, %2;" : "=f"(lo), "=f"(hi) : "l"(v));
}

// one 8->8 transform with packed output pairs: o2[a2] = (o[2a2], o[2a2+1])
__device__ __forceinline__ void xform8(const u64t* __restrict__ m2,
                                       const float* __restrict__ x,
                                       u64t* __restrict__ o2) {
    u64t xp[8];
    #pragma unroll
    for (int n = 0; n < 8; ++n) xp[n] = pk2(x[n], x[n]);
    #pragma unroll
    for (int a2 = 0; a2 < 4; ++a2) {
        u64t acc = 0ULL;
        #pragma unroll
        for (int n = 0; n < 8; ++n) acc = fma2(m2[a2 * 8 + n], xp[n], acc);
        o2[a2] = acc;
    }
}

__device__ __forceinline__ void build_m2(const float* __restrict__ M, u64t* m2) {
    #pragma unroll
    for (int a2 = 0; a2 < 4; ++a2)
        #pragma unroll
        for (int n = 0; n < 8; ++n)
            m2[a2 * 8 + n] = pk2(M[(2 * a2) * 8 + n], M[(2 * a2 + 1) * 8 + n]);
}

__global__ void __launch_bounds__(256, 2)
qconv_kernel(const float* __restrict__ rho,
             const float* __restrict__ ux,
             const float* __restrict__ uy,
             const float* __restrict__ uc,
             float* __restrict__ out)
{
    extern __shared__ float s[];
    float* buf = s;
    const int b = blockIdx.x;
    const int t = threadIdx.x;

    if (t < 64) { s[SM_UY + t] = uy[t]; s[SM_UX + t] = ux[t]; }
    else if (t < 72) { int q = t - 64; s[SM_UC + q] = uc[(q >> 1) * 4 + 2 + (q & 1)]; }
    __syncthreads();

    u64t m2[32];

    // ===== P1': gmem load fused with right-uy (contiguous j') ================
    build_m2(s + SM_UY, m2);
    {
        const float4* src = (const float4*)(rho + (size_t)b * 16384);
        #pragma unroll
        for (int it = 0; it < 8; ++it) {
            int idx = t + it * 256;            // 0..2047, group = 8 floats at idx*8
            float4 q0 = src[idx * 2];
            float4 q1 = src[idx * 2 + 1];
            float x[8] = {q0.x, q0.y, q0.z, q0.w, q1.x, q1.y, q1.z, q1.w};
            u64t o2[4];
            xform8(m2, x, o2);
            int r = idx >> 4, sub = idx & 15;
            float* g = buf + r * PSTR + sub * 8;
            #pragma unroll
            for (int a2 = 0; a2 < 4; ++a2)
                *(u64t*)(g + 2 * a2) = o2[a2];   // contiguous pair, 8B aligned
        }
    }
    __syncthreads();

    // ===== P2: left uy (stride PSTR) — same m2 =============================
    {
        #pragma unroll
        for (int it = 0; it < 8; ++it) {
            int idx = t + it * 256;
            int f = idx >> 10, i8 = (idx >> 7) & 7, c = idx & 127;
            float* g = buf + (f * 64 + i8 * 8) * PSTR + c;
            float x[8];
            #pragma unroll
            for (int n = 0; n < 8; ++n) x[n] = g[n * PSTR];
            u64t o2[4];
            xform8(m2, x, o2);
            #pragma unroll
            for (int a2 = 0; a2 < 4; ++a2) {
                float lo, hi; upk2(o2[a2], lo, hi);
                g[(2 * a2) * PSTR] = lo;
                g[(2 * a2 + 1) * PSTR] = hi;
            }
        }
    }
    __syncthreads();

    // ===== P3: right ux (stride 8) =========================================
    build_m2(s + SM_UX, m2);
    {
        #pragma unroll
        for (int it = 0; it < 8; ++it) {
            int idx = t + it * 256;
            int fp = idx >> 10, rem = idx & 1023;
            int r = rem >> 3, j = rem & 7;        // lane = (r&3)*8 | j -> 32 banks
            float* g = buf + r * PSTR + fp * 64 + j;
            float x[8];
            #pragma unroll
            for (int n = 0; n < 8; ++n) x[n] = g[n * 8];
            u64t o2[4];
            xform8(m2, x, o2);
            #pragma unroll
            for (int a2 = 0; a2 < 4; ++a2) {
                float lo, hi; upk2(o2[a2], lo, hi);
                g[(2 * a2) * 8] = lo;
                g[(2 * a2 + 1) * 8] = hi;
            }
        }
    }
    __syncthreads();

    // ===== P4: left ux (stride 8*PSTR) — same m2 ===========================
    {
        #pragma unroll
        for (int it = 0; it < 8; ++it) {
            int idx = t + it * 256;
            int f = idx >> 10, j = (idx >> 7) & 7, c = idx & 127;
            float* g = buf + (f * 64 + j) * PSTR + c;
            float x[8];
            #pragma unroll
            for (int n = 0; n < 8; ++n) x[n] = g[n * 8 * PSTR];
            u64t o2[4];
            xform8(m2, x, o2);
            #pragma unroll
            for (int a2 = 0; a2 < 4; ++a2) {
                float lo, hi; upk2(o2[a2], lo, hi);
                g[(2 * a2) * 8 * PSTR] = lo;
                g[(2 * a2 + 1) * 8 * PSTR] = hi;
            }
        }
    }
    __syncthreads();

    // ===== epilogue: out[gv, g'v'] = sum_{f,f'} c[g,f] c[g',f'] M[fv, f'v'] ==
    {
        const int wid = t >> 5, lane = t & 31;
        const int vp0 = (lane & 15) * 4;
        float* outb = out + (size_t)b * 65536;
        float cg0[4], cg1[4];
        #pragma unroll
        for (int g = 0; g < 4; ++g) {
            cg0[g] = s[SM_UC + g * 2];
            cg1[g] = s[SM_UC + g * 2 + 1];
        }

        #pragma unroll 1
        for (int rr = 0; rr < 32; ++rr) {
            const int p = wid * 32 + rr;       // output row 0..255
            const int g = p >> 6, v = p & 63;
            const float a0 = cg0[g], a1 = cg1[g];
            const float* row0 = buf + v * PSTR;          // f = 0
            const float* row1 = buf + (64 + v) * PSTR;   // f = 1
            float4 m00 = *(const float4*)(row0 + vp0);        // f'=0
            float4 m01 = *(const float4*)(row0 + 64 + vp0);   // f'=1
            float4 m10 = *(const float4*)(row1 + vp0);
            float4 m11 = *(const float4*)(row1 + 64 + vp0);
            float4 t0, t1;
            t0.x = fmaf(a1, m10.x, a0 * m00.x);
            t0.y = fmaf(a1, m10.y, a0 * m00.y);
            t0.z = fmaf(a1, m10.z, a0 * m00.z);
            t0.w = fmaf(a1, m10.w, a0 * m00.w);
            t1.x = fmaf(a1, m11.x, a0 * m01.x);
            t1.y = fmaf(a1, m11.y, a0 * m01.y);
            t1.z = fmaf(a1, m11.z, a0 * m01.z);
            t1.w = fmaf(a1, m11.w, a0 * m01.w);
            #pragma unroll
            for (int it = 0; it < 2; ++it) {
                const int gp = (it << 1) | (lane >> 4);
                const float p0 = cg0[gp], p1 = cg1[gp];
                float4 o;
                o.x = fmaf(p1, t1.x, p0 * t0.x);
                o.y = fmaf(p1, t1.y, p0 * t0.y);
                o.z = fmaf(p1, t1.z, p0 * t0.z);
                o.w = fmaf(p1, t1.w, p0 * t0.w);
                *(float4*)(outb + p * 256 + gp * 64 + vp0) = o;
            }
        }
    }
}

extern "C" void kernel_launch(void* const* d_in, const int* in_sizes, int n_in,
                              void* d_out, int out_size) {
    const float* rho = (const float*)d_in[0];
    const float* ux  = (const float*)d_in[1];
    const float* uy  = (const float*)d_in[2];
    const float* uc  = (const float*)d_in[3];
    float* out = (float*)d_out;

    const int B = in_sizes[0] >> 14;   // elements / (128*128)

    cudaFuncSetAttribute(qconv_kernel,
                         cudaFuncAttributeMaxDynamicSharedMemorySize, SMEM_BYTES);
    qconv_kernel<<<B, 256, SMEM_BYTES>>>(rho, ux, uy, uc, out);
}